// round 1
// baseline (speedup 1.0000x reference)
#include <cuda_runtime.h>

#define BETA      0.99f
#define NUM_STEPS 50
#define B_DIM     8192
#define IN_DIM    512
#define OUT_DIM   256

// 8 MB scratch for injected current (allocation-free rule: device global).
__device__ float g_cur[(size_t)B_DIM * OUT_DIM];

// ---------------------------------------------------------------------------
// Kernel 1: cur = x @ W^T + bias      (M=8192, N=256, K=512, fp32)
// Classic smem-tiled SIMT GEMM. K accumulated strictly in ascending order to
// stay close to the reference's sequential fp32 summation.
// ---------------------------------------------------------------------------
#define BM 128
#define BN 64
#define BK 32
#define TM 8
#define TN 4
// threads = (BM/TM) * (BN/TN) = 16 * 16 = 256

__global__ __launch_bounds__(256) void gemm_kernel()
{
    // set by kernel_launch via __constant__? simpler: pointers passed as params
}

__global__ __launch_bounds__(256) void gemm_xwt_kernel(
    const float* __restrict__ x,     // [B_DIM, IN_DIM]
    const float* __restrict__ W,     // [OUT_DIM, IN_DIM]
    const float* __restrict__ bias)  // [OUT_DIM]
{
    __shared__ float As[BM][BK + 4];   // +4 pad: kill LDS bank conflicts
    __shared__ float Bs[BN][BK + 4];

    const int tid  = threadIdx.x;
    const int tx   = tid % 16;          // N direction (TN=4 -> covers 64)
    const int ty   = tid / 16;          // M direction (TM=8 -> covers 128)
    const int row0 = blockIdx.y * BM;
    const int col0 = blockIdx.x * BN;

    float acc[TM][TN];
#pragma unroll
    for (int i = 0; i < TM; i++)
#pragma unroll
        for (int j = 0; j < TN; j++) acc[i][j] = 0.0f;

    for (int k0 = 0; k0 < IN_DIM; k0 += BK) {
        // Load A tile: 128 x 32 floats = 1024 float4, 4 per thread.
#pragma unroll
        for (int l = 0; l < (BM * BK) / (256 * 4); l++) {
            int idx = tid + l * 256;          // float4 index
            int r   = idx / (BK / 4);         // BK/4 = 8 float4 per row
            int c   = (idx % (BK / 4)) * 4;
            float4 v = *reinterpret_cast<const float4*>(
                &x[(size_t)(row0 + r) * IN_DIM + k0 + c]);
            As[r][c + 0] = v.x; As[r][c + 1] = v.y;
            As[r][c + 2] = v.z; As[r][c + 3] = v.w;
        }
        // Load B tile: 64 x 32 floats = 512 float4, 2 per thread.
#pragma unroll
        for (int l = 0; l < (BN * BK) / (256 * 4); l++) {
            int idx = tid + l * 256;
            int r   = idx / (BK / 4);
            int c   = (idx % (BK / 4)) * 4;
            float4 v = *reinterpret_cast<const float4*>(
                &W[(size_t)(col0 + r) * IN_DIM + k0 + c]);
            Bs[r][c + 0] = v.x; Bs[r][c + 1] = v.y;
            Bs[r][c + 2] = v.z; Bs[r][c + 3] = v.w;
        }
        __syncthreads();

#pragma unroll
        for (int k = 0; k < BK; k++) {
            float a[TM], bv[TN];
#pragma unroll
            for (int i = 0; i < TM; i++) a[i] = As[ty * TM + i][k];
#pragma unroll
            for (int j = 0; j < TN; j++) bv[j] = Bs[tx * TN + j][k];
#pragma unroll
            for (int i = 0; i < TM; i++)
#pragma unroll
                for (int j = 0; j < TN; j++)
                    acc[i][j] = fmaf(a[i], bv[j], acc[i][j]);
        }
        __syncthreads();
    }

#pragma unroll
    for (int i = 0; i < TM; i++) {
        int r = row0 + ty * TM + i;
#pragma unroll
        for (int j = 0; j < TN; j++) {
            int c = col0 + tx * TN + j;
            g_cur[(size_t)r * OUT_DIM + c] = acc[i][j] + bias[c];
        }
    }
}

// ---------------------------------------------------------------------------
// Kernel 2: 50-step LIF recurrence + transposed spike writeout.
// One thread owns one (b, o) trajectory (recurrence is serial in t).
// Spikes staged in smem [thread][t], then linear float4 copy-out so all
// HBM stores are fully coalesced STG.128.
// ---------------------------------------------------------------------------
#define SNN_THREADS 128   // smem = 128*50*4 = 25600 B (< 48 KB static limit)

__global__ __launch_bounds__(SNN_THREADS) void snn_kernel(float* __restrict__ out)
{
    __shared__ float s[SNN_THREADS * NUM_STEPS];

    const int half = blockIdx.x & 1;          // which 128-wide half of OUT
    const int b    = blockIdx.x >> 1;
    const int o    = half * SNN_THREADS + threadIdx.x;

    const float c = g_cur[(size_t)b * OUT_DIM + o];

    float  mem = 0.0f;
    float* row = &s[threadIdx.x * NUM_STEPS];

#pragma unroll
    for (int t = 0; t < NUM_STEPS; t++) {
        // reset based on membrane BEFORE update (subtract mechanism)
        float reset = (mem > 1.0f) ? 1.0f : 0.0f;
        // mem = BETA*mem + cur - reset  -- match reference eval order, no fusion
        mem = __fadd_rn(__fadd_rn(__fmul_rn(BETA, mem), c), -reset);
        row[t] = (mem > 1.0f) ? 1.0f : 0.0f;
    }
    __syncthreads();

    // Block's output region is contiguous: blockIdx.x * (128*50) floats.
    // out[b][o][t] = out[b*OUT_DIM*T + o*T + t]; region start
    //   b*256*50 + half*128*50 = blockIdx.x * 6400. 25600 B -> 16B aligned.
    float4*       out4 = reinterpret_cast<float4*>(
        out + (size_t)blockIdx.x * (SNN_THREADS * NUM_STEPS));
    const float4* s4   = reinterpret_cast<const float4*>(s);
#pragma unroll 4
    for (int i = threadIdx.x; i < (SNN_THREADS * NUM_STEPS) / 4; i += SNN_THREADS)
        out4[i] = s4[i];
}

// ---------------------------------------------------------------------------
extern "C" void kernel_launch(void* const* d_in, const int* in_sizes, int n_in,
                              void* d_out, int out_size)
{
    const float* x    = (const float*)d_in[0];   // [8192, 512]
    const float* W    = (const float*)d_in[1];   // [256, 512]
    const float* bias = (const float*)d_in[2];   // [256]
    float*       out  = (float*)d_out;           // [8192, 256, 50]

    dim3 gemm_grid(OUT_DIM / BN, B_DIM / BM);    // (4, 64) = 256 blocks
    gemm_xwt_kernel<<<gemm_grid, 256>>>(x, W, bias);

    snn_kernel<<<B_DIM * 2, SNN_THREADS>>>(out);
}

// round 3
// speedup vs baseline: 1.0373x; 1.0373x over previous
#include <cuda_runtime.h>
#include <stdint.h>

#define BETA      0.99f
#define NUM_STEPS 50
#define B_DIM     8192
#define IN_DIM    512
#define OUT_DIM   256

// Tile: 64 x 64 outputs per block, 256 threads, TM=TN=4.
#define TILE      64
#define BK        16
#define ROW_ELEMS (OUT_DIM * NUM_STEPS)   // 12800 floats per batch row

__global__ __launch_bounds__(256, 2) void snn_fused_kernel(
    const float* __restrict__ x,     // [B_DIM, IN_DIM]
    const float* __restrict__ W,     // [OUT_DIM, IN_DIM]
    const float* __restrict__ bias,  // [OUT_DIM]
    float* __restrict__ out)         // [B_DIM, OUT_DIM, NUM_STEPS]
{
    // k-major tiles for vectorized inner loads (68 = 17 float4 -> 16B aligned rows)
    __shared__ float As[BK][68];
    __shared__ float Bs[BK][68];
    __shared__ uint32_t s_msk[TILE * TILE * 2];   // [r][c][{lo,hi}]  32 KB

    const int tid  = threadIdx.x;
    const int tx   = tid & 15;          // col group (4 cols each)
    const int ty   = tid >> 4;          // row group (4 rows each)
    const int col0 = blockIdx.x * TILE;
    const int row0 = blockIdx.y * TILE;

    // ---------------- GEMM phase: cur = x @ W^T + b ----------------
    float acc[16];
#pragma unroll
    for (int e = 0; e < 16; e++) acc[e] = 0.0f;

    const int lr = tid >> 2;            // load row within tile (0..63)
    const int lc = (tid & 3) << 2;      // load col within k-chunk (0,4,8,12)
    const float* xp = x + (size_t)(row0 + lr) * IN_DIM + lc;
    const float* wp = W + (size_t)(col0 + lr) * IN_DIM + lc;

    for (int k0 = 0; k0 < IN_DIM; k0 += BK) {
        float4 va = *reinterpret_cast<const float4*>(xp + k0);
        float4 vb = *reinterpret_cast<const float4*>(wp + k0);
        As[lc + 0][lr] = va.x; As[lc + 1][lr] = va.y;
        As[lc + 2][lr] = va.z; As[lc + 3][lr] = va.w;
        Bs[lc + 0][lr] = vb.x; Bs[lc + 1][lr] = vb.y;
        Bs[lc + 2][lr] = vb.z; Bs[lc + 3][lr] = vb.w;
        __syncthreads();

#pragma unroll
        for (int kk = 0; kk < BK; kk++) {
            float4 a = *reinterpret_cast<const float4*>(&As[kk][ty << 2]);
            float4 b = *reinterpret_cast<const float4*>(&Bs[kk][tx << 2]);
            float av[4] = {a.x, a.y, a.z, a.w};
            float bv[4] = {b.x, b.y, b.z, b.w};
#pragma unroll
            for (int i = 0; i < 4; i++)
#pragma unroll
                for (int j = 0; j < 4; j++)
                    acc[i * 4 + j] = fmaf(av[i], bv[j], acc[i * 4 + j]);
        }
        __syncthreads();
    }

    // bias (one LDG.128)
    float4 b4 = *reinterpret_cast<const float4*>(&bias[col0 + (tx << 2)]);
    float bb[4] = {b4.x, b4.y, b4.z, b4.w};
#pragma unroll
    for (int i = 0; i < 4; i++)
#pragma unroll
        for (int j = 0; j < 4; j++)
            acc[i * 4 + j] = acc[i * 4 + j] + bb[j];

    // ---------------- LIF recurrence: 16 trajectories in registers ----------
    // reset_t == spike_{t-1}; arithmetic order matches round-1 exactly:
    //   mem = ((BETA*mem) + cur) + (-spk_prev)
    float    mem[16], spk[16];
    uint32_t lo[16], hi[16];
#pragma unroll
    for (int e = 0; e < 16; e++) { mem[e] = 0.0f; spk[e] = 0.0f; lo[e] = 0u; hi[e] = 0u; }

#pragma unroll 2
    for (int t = 0; t < 32; t++) {
#pragma unroll
        for (int e = 0; e < 16; e++) {
            mem[e] = __fadd_rn(__fadd_rn(__fmul_rn(BETA, mem[e]), acc[e]), -spk[e]);
            bool s = mem[e] > 1.0f;
            spk[e] = s ? 1.0f : 0.0f;
            lo[e] |= (s ? 1u : 0u) << t;
        }
    }
#pragma unroll 2
    for (int t = 32; t < NUM_STEPS; t++) {
#pragma unroll
        for (int e = 0; e < 16; e++) {
            mem[e] = __fadd_rn(__fadd_rn(__fmul_rn(BETA, mem[e]), acc[e]), -spk[e]);
            bool s = mem[e] > 1.0f;
            spk[e] = s ? 1.0f : 0.0f;
            hi[e] |= (s ? 1u : 0u) << (t - 32);
        }
    }

    // masks -> smem: s_msk[(r*64 + c)*2 + {0,1}]
#pragma unroll
    for (int i = 0; i < 4; i++) {
#pragma unroll
        for (int j = 0; j < 4; j++) {
            int r = (ty << 2) + i, c = (tx << 2) + j;
            uint2 m = make_uint2(lo[i * 4 + j], hi[i * 4 + j]);
            *reinterpret_cast<uint2*>(&s_msk[((r << 6) + c) << 1]) = m;
        }
    }
    __syncthreads();

    // ---------------- Expansion + coalesced writeout ----------------
    // warp w handles rows [8w, 8w+8). Per row: 64 cols x 50 steps = 3200 floats.
    // Organized as 32 groups of 2 cols (100 floats = 25 float4); lanes 0..24 active.
    // Per-lane constants (independent of row/cc): element idx = lane*4+u in [0,100)
    //   c_off = idx>=50, t = idx-50*c_off, word = t>>5, shift = t&31.
    const int lane = tid & 31;
    const int warp = tid >> 5;
    const bool active = lane < 25;

    int woff[4];   // uint32 offset within a 2-col group: c_off*2 + word
    int shf[4];
#pragma unroll
    for (int u = 0; u < 4; u++) {
        int idx = lane * 4 + u;
        int cf  = (idx >= 50) ? 1 : 0;
        int t   = idx - 50 * cf;
        woff[u] = (cf << 1) + (t >> 5);
        shf[u]  = t & 31;
    }

#pragma unroll
    for (int rr = 0; rr < 8; rr++) {
        int row = (warp << 3) + rr;
        const uint32_t* mrow = s_msk + (row << 7);                  // 64 cols * 2 words
        float4* gout = reinterpret_cast<float4*>(
            out + (size_t)(row0 + row) * ROW_ELEMS + (size_t)col0 * NUM_STEPS);
        if (active) {
#pragma unroll 4
            for (int cc = 0; cc < 32; cc++) {
                const uint32_t* g = mrow + (cc << 2);               // 2 cols = 4 words
                float4 v;
                v.x = __uint_as_float(((g[woff[0]] >> shf[0]) & 1u) * 0x3f800000u);
                v.y = __uint_as_float(((g[woff[1]] >> shf[1]) & 1u) * 0x3f800000u);
                v.z = __uint_as_float(((g[woff[2]] >> shf[2]) & 1u) * 0x3f800000u);
                v.w = __uint_as_float(((g[woff[3]] >> shf[3]) & 1u) * 0x3f800000u);
                gout[cc * 25 + lane] = v;
            }
        }
    }
}

extern "C" void kernel_launch(void* const* d_in, const int* in_sizes, int n_in,
                              void* d_out, int out_size)
{
    const float* x    = (const float*)d_in[0];   // [8192, 512]
    const float* W    = (const float*)d_in[1];   // [256, 512]
    const float* bias = (const float*)d_in[2];   // [256]
    float*       out  = (float*)d_out;           // [8192, 256, 50]

    dim3 grid(OUT_DIM / TILE, B_DIM / TILE);     // (4, 128) = 512 blocks
    snn_fused_kernel<<<grid, 256>>>(x, W, bias, out);
}

// round 5
// speedup vs baseline: 1.3381x; 1.2900x over previous
#include <cuda_runtime.h>
#include <stdint.h>

#define BETA      0.99f
#define T50       50
#define B_DIM     8192
#define IN_DIM    512
#define OUT_DIM   256

#define TILE_M    64          // batch rows per block
#define TILE_N    32          // output cols per block
#define BK        16
#define ROW_ELEMS (OUT_DIM * T50)   // 12800 floats per batch row

__global__ __launch_bounds__(128, 6) void snn_fused2(
    const float* __restrict__ x,     // [B_DIM, IN_DIM]
    const float* __restrict__ W,     // [OUT_DIM, IN_DIM]
    const float* __restrict__ bias,  // [OUT_DIM]
    float* __restrict__ out)         // [B_DIM, OUT_DIM, T50]
{
    __shared__ float As[BK][68];                // k-major, padded
    __shared__ float Bs[BK][36];
    __shared__ uint32_t s_msk[TILE_M * TILE_N * 2];   // 16 KB: [r][c][{lo,hi}]

    const int tid  = threadIdx.x;
    const int tx   = tid & 7;           // col group (4 cols each -> 32)
    const int ty   = tid >> 3;          // row group (4 rows each -> 64)
    const int col0 = blockIdx.x * TILE_N;
    const int row0 = blockIdx.y * TILE_M;

    // ---------------- GEMM: cur = x @ W^T + b  (k strictly ascending) -------
    float acc[16];
#pragma unroll
    for (int e = 0; e < 16; e++) acc[e] = 0.0f;

    const int lr = tid >> 2;            // 0..31
    const int lc = (tid & 3) << 2;      // 0,4,8,12
    const float* xp0 = x + (size_t)(row0 + lr) * IN_DIM + lc;
    const float* xp1 = xp0 + (size_t)32 * IN_DIM;
    const float* wp0 = W + (size_t)(col0 + lr) * IN_DIM + lc;

    // prefetch first k-chunk
    float4 va0 = *reinterpret_cast<const float4*>(xp0);
    float4 va1 = *reinterpret_cast<const float4*>(xp1);
    float4 vb0 = *reinterpret_cast<const float4*>(wp0);

    for (int k0 = 0; k0 < IN_DIM; k0 += BK) {
        As[lc + 0][lr]      = va0.x; As[lc + 1][lr]      = va0.y;
        As[lc + 2][lr]      = va0.z; As[lc + 3][lr]      = va0.w;
        As[lc + 0][lr + 32] = va1.x; As[lc + 1][lr + 32] = va1.y;
        As[lc + 2][lr + 32] = va1.z; As[lc + 3][lr + 32] = va1.w;
        Bs[lc + 0][lr]      = vb0.x; Bs[lc + 1][lr]      = vb0.y;
        Bs[lc + 2][lr]      = vb0.z; Bs[lc + 3][lr]      = vb0.w;
        __syncthreads();

        if (k0 + BK < IN_DIM) {         // prefetch next chunk under the FFMAs
            va0 = *reinterpret_cast<const float4*>(xp0 + k0 + BK);
            va1 = *reinterpret_cast<const float4*>(xp1 + k0 + BK);
            vb0 = *reinterpret_cast<const float4*>(wp0 + k0 + BK);
        }

#pragma unroll
        for (int kk = 0; kk < BK; kk++) {
            float4 a = *reinterpret_cast<const float4*>(&As[kk][ty << 2]);
            float4 b = *reinterpret_cast<const float4*>(&Bs[kk][tx << 2]);
            float av[4] = {a.x, a.y, a.z, a.w};
            float bv[4] = {b.x, b.y, b.z, b.w};
#pragma unroll
            for (int i = 0; i < 4; i++)
#pragma unroll
                for (int j = 0; j < 4; j++)
                    acc[i * 4 + j] = fmaf(av[i], bv[j], acc[i * 4 + j]);
        }
        __syncthreads();
    }

    {   // bias add (same op as round-1/3: plain fp32 add)
        float4 b4 = *reinterpret_cast<const float4*>(&bias[col0 + (tx << 2)]);
        float bb[4] = {b4.x, b4.y, b4.z, b4.w};
#pragma unroll
        for (int i = 0; i < 4; i++)
#pragma unroll
            for (int j = 0; j < 4; j++)
                acc[i * 4 + j] = acc[i * 4 + j] + bb[j];
    }

    // ---------------- LIF recurrence: 4 chunks of 4 trajectories ------------
    // Bit-exact vs round-1: mem = fadd(fadd(fmul(B,mem),c), -spk) and
    // fadd(X,-0)==X, fadd(X,-1) when spiked -> predicated subtract is identical.
#pragma unroll
    for (int i = 0; i < 4; i++) {
        float c0 = acc[i * 4 + 0], c1 = acc[i * 4 + 1];
        float c2 = acc[i * 4 + 2], c3 = acc[i * 4 + 3];
        float m0 = 0.f, m1 = 0.f, m2 = 0.f, m3 = 0.f;
        bool  s0 = false, s1 = false, s2 = false, s3 = false;
        uint32_t lo0 = 0, lo1 = 0, lo2 = 0, lo3 = 0;
        uint32_t hi0 = 0, hi1 = 0, hi2 = 0, hi3 = 0;

#pragma unroll
        for (int t = 0; t < T50; t++) {
            float t0 = __fadd_rn(__fmul_rn(BETA, m0), c0);
            float t1 = __fadd_rn(__fmul_rn(BETA, m1), c1);
            float t2 = __fadd_rn(__fmul_rn(BETA, m2), c2);
            float t3 = __fadd_rn(__fmul_rn(BETA, m3), c3);
            m0 = s0 ? __fadd_rn(t0, -1.0f) : t0;
            m1 = s1 ? __fadd_rn(t1, -1.0f) : t1;
            m2 = s2 ? __fadd_rn(t2, -1.0f) : t2;
            m3 = s3 ? __fadd_rn(t3, -1.0f) : t3;
            s0 = m0 > 1.0f; s1 = m1 > 1.0f; s2 = m2 > 1.0f; s3 = m3 > 1.0f;
            if (t < 32) {
                lo0 |= s0 ? (1u << t) : 0u; lo1 |= s1 ? (1u << t) : 0u;
                lo2 |= s2 ? (1u << t) : 0u; lo3 |= s3 ? (1u << t) : 0u;
            } else {
                hi0 |= s0 ? (1u << (t - 32)) : 0u; hi1 |= s1 ? (1u << (t - 32)) : 0u;
                hi2 |= s2 ? (1u << (t - 32)) : 0u; hi3 |= s3 ? (1u << (t - 32)) : 0u;
            }
        }

        int r    = (ty << 2) + i;
        int base = ((r << 5) + (tx << 2)) << 1;     // (r*32 + c)*2
        *reinterpret_cast<uint2*>(&s_msk[base + 0]) = make_uint2(lo0, hi0);
        *reinterpret_cast<uint2*>(&s_msk[base + 2]) = make_uint2(lo1, hi1);
        *reinterpret_cast<uint2*>(&s_msk[base + 4]) = make_uint2(lo2, hi2);
        *reinterpret_cast<uint2*>(&s_msk[base + 6]) = make_uint2(lo3, hi3);
    }
    __syncthreads();

    // ---------------- Expansion + coalesced streaming writeout --------------
    // Warp w owns rows [16w, 16w+16). Per row: 32 cols x 50 = 1600 floats
    // = 16 groups of 2 cols (100 floats = 25 float4); lanes 0..24 active.
    const int lane = tid & 31;
    const int warp = tid >> 5;

    int woff[4], shf[4];
#pragma unroll
    for (int u = 0; u < 4; u++) {
        int idx = lane * 4 + u;
        int cf  = (idx >= 50) ? 1 : 0;
        int t   = idx - 50 * cf;
        woff[u] = (cf << 1) + (t >> 5);
        shf[u]  = t & 31;
    }

    if (lane < 25) {
#pragma unroll
        for (int rr = 0; rr < 16; rr++) {
            int row = (warp << 4) + rr;
            const uint32_t* mrow = s_msk + (row << 6);      // 32 cols * 2 words
            float4* gout = reinterpret_cast<float4*>(
                out + (size_t)(row0 + row) * ROW_ELEMS + (size_t)col0 * T50);
#pragma unroll 4
            for (int cc = 0; cc < 16; cc++) {
                const uint32_t* g = mrow + (cc << 2);       // 2 cols = 4 words
                float4 v;
                v.x = __uint_as_float(((g[woff[0]] >> shf[0]) & 1u) * 0x3f800000u);
                v.y = __uint_as_float(((g[woff[1]] >> shf[1]) & 1u) * 0x3f800000u);
                v.z = __uint_as_float(((g[woff[2]] >> shf[2]) & 1u) * 0x3f800000u);
                v.w = __uint_as_float(((g[woff[3]] >> shf[3]) & 1u) * 0x3f800000u);
                __stcs(&gout[cc * 25 + lane], v);           // streaming: skip L2 persist
            }
        }
    }
}

extern "C" void kernel_launch(void* const* d_in, const int* in_sizes, int n_in,
                              void* d_out, int out_size)
{
    const float* x    = (const float*)d_in[0];   // [8192, 512]
    const float* W    = (const float*)d_in[1];   // [256, 512]
    const float* bias = (const float*)d_in[2];   // [256]
    float*       out  = (float*)d_out;           // [8192, 256, 50]

    dim3 grid(OUT_DIM / TILE_N, B_DIM / TILE_M); // (8, 128) = 1024 blocks
    snn_fused2<<<grid, 128>>>(x, W, bias, out);
}